// round 8
// baseline (speedup 1.0000x reference)
#include <cuda_runtime.h>

// EPG / RF-spoiled SPGR: rotating-frame formulation, round 8.
// Changes vs R7: negated packed constants replaced by XOR sign-flips on the
// ALU pipe (frees 8 regs + 1 fma-pipe mul/pulse); __launch_bounds__(256,6)
// to lift occupancy 5 -> 6 blocks/SM.
// State (S, D, Z), S = F̂p+F̂m, D = F̂p−F̂m, frame F̂p = e^{-i phi}Fp,
// F̂m = e^{+i phi}Fm. RF = real 2x2 (D,Z) mix; S invariant. Phase enters as
// e^{±i delta_p} at the shift (delta exact fp32) + e^{-2i phi'} on the
// Fm[1]->Fp[0] element. One warp/voxel; lane l holds pair {2l,2l+1} (f32x2).
// Truncation (pre-shift: Fp kill k>=49, Fm kill k>=50) via 64-bit ANDs.

#define FULLMASK 0xffffffffu
typedef unsigned long long u64;
#define NP 200
#define SGN2 0x8000000080000000ULL

// g_tab[2p]   = {cos d, cos d, sin d, sin d}   (d = delta_p)
// g_tab[2p+1] = {cos 2phi_{p+1}, sin 2phi_{p+1}, 0, 0}
__device__ ulonglong2 g_tab[2 * NP];

__global__ void trig_init_kernel() {
    int p = threadIdx.x + blockIdx.x * blockDim.x;
    if (p >= NP) return;
    const float SPOIL = 2.0420352248333655f;  // float32(deg2rad(117))
    float phi = 0.f, inc = 0.f;
    for (int j = 0; j < p; ++j) { inc += SPOIL; phi += inc; }   // phi_p, exact ref order
    float phin = phi + (inc + SPOIL);                            // phi_{p+1}
    float d = phin - phi;                                        // exact subtraction
    float sd, cd;  sincosf(d, &sd, &cd);
    float s2p, c2p; sincosf(2.0f * phin, &s2p, &c2p);
    float4* f4 = reinterpret_cast<float4*>(g_tab);
    f4[2 * p]     = make_float4(cd, cd, sd, sd);
    f4[2 * p + 1] = make_float4(c2p, s2p, 0.f, 0.f);
}

static __device__ __forceinline__ u64 pk2(float lo, float hi) {
    u64 r; asm("mov.b64 %0, {%1, %2};" : "=l"(r) : "f"(lo), "f"(hi)); return r;
}
static __device__ __forceinline__ void upk2(u64 v, float& lo, float& hi) {
    asm("mov.b64 {%0, %1}, %2;" : "=f"(lo), "=f"(hi) : "l"(v));
}
static __device__ __forceinline__ u64 f2fma(u64 a, u64 b, u64 c) {
    u64 d; asm("fma.rn.f32x2 %0, %1, %2, %3;" : "=l"(d) : "l"(a), "l"(b), "l"(c)); return d;
}
static __device__ __forceinline__ u64 f2mul(u64 a, u64 b) {
    u64 d; asm("mul.rn.f32x2 %0, %1, %2;" : "=l"(d) : "l"(a), "l"(b)); return d;
}
static __device__ __forceinline__ u64 f2add(u64 a, u64 b) {
    u64 d; asm("add.rn.f32x2 %0, %1, %2;" : "=l"(d) : "l"(a), "l"(b)); return d;
}

__global__ void __launch_bounds__(256, 6)
epg_kernel(const float* __restrict__ T1, const float* __restrict__ T2,
           const float* __restrict__ alpha, const float* __restrict__ TR,
           float* __restrict__ out, int n)
{
    __shared__ ulonglong2 s_tab[2 * NP];
    for (int i = threadIdx.x; i < 2 * NP; i += blockDim.x) s_tab[i] = g_tab[i];
    __syncthreads();

    const int v    = (blockIdx.x * blockDim.x + threadIdx.x) >> 5;
    const int lane = threadIdx.x & 31;
    if (v >= n) return;

    const float TRv = TR[0];
    const float E1  = expf(-TRv / T1[v]);
    const float E2  = expf(-TRv / T2[v]);
    const float a   = alpha[v];
    float sa, ca; sincosf(a, &sa, &ca);

    const float E2h   = 0.5f * E2;
    const float sa2   = 2.0f * sa;
    const float saE1h = 0.5f * sa * E1;
    const float caE1  = ca * E1;

    const u64 caP     = pk2(ca, ca);
    const u64 sa2P    = pk2(sa2, sa2);
    const u64 caE1P   = pk2(caE1, caE1);
    const u64 saE1hP  = pk2(saE1h, saE1h);
    const u64 E2hP    = pk2(E2h, E2h);
    const u64 nOneP   = pk2(-1.f, -1.f);
    const u64 boostP  = pk2(lane == 0 ? 1.f - E1 : 0.f, 0.f);

    // Truncation masks (pre-shift): Fp-path kill k>=49, Fm-path kill k>=50.
    const int kLo = 2 * lane, kHi = 2 * lane + 1;
    const u64 mFp = (kLo <= 48 ? 0xffffffffull : 0ull) | (kHi <= 48 ? 0xffffffff00000000ull : 0ull);
    const u64 mFm = (kLo <= 49 ? 0xffffffffull : 0ull) | (kHi <= 49 ? 0xffffffff00000000ull : 0ull);

    // Rotating-frame state {k=2l, k=2l+1}: S = F̂p+F̂m, D = F̂p-F̂m, Z.
    u64 Sr = 0, Si = 0, Dr = 0, Di = 0;
    u64 Zr = pk2(lane == 0 ? 1.f : 0.f, 0.f), Zi = 0;

    #pragma unroll 4
    for (int p = 0; p < NP - 1; ++p) {
        const ulonglong2 T = s_tab[2 * p];          // {cd,cd},{sd,sd}
        const u64 cdP = T.x, sdP = T.y;
        float sp_c, sp_s;                           // {cos 2phi', sin 2phi'}
        upk2(s_tab[2 * p + 1].x, sp_c, sp_s);

        // Per-pulse coefficients: A = E2h * e^{-i d}  (Ar=cA, Ai=-sA)
        const u64 cA  = f2mul(E2hP, cdP);
        const u64 sA  = f2mul(E2hP, sdP);
        const u64 nsA = sA ^ SGN2;                  // ALU negate

        // RF rotation (frame): D'' = ca*D - 2i*sa*Z
        //   D''r = ca*Dr + sa2*Zi ; D''i = ca*Di - sa2*Zr
        const u64 DDr = f2fma(caP, Dr, f2mul(sa2P, Zi));
        const u64 DDi = f2fma(caP, Di, f2mul(sa2P, Zr) ^ SGN2);
        // Z_next = E1*(ca*Z - 0.5i*sa*D) + boost
        const u64 nZr = f2fma(caE1P, Zr, f2fma(saE1hP, Di, boostP));
        const u64 nZi = f2fma(caE1P, Zi, f2mul(saE1hP, Dr) ^ SGN2);

        // W = S + D'' (= 2*Fp_rf),  X = S - D'' (= 2*Fm_rf)
        const u64 Wr = f2add(Sr, DDr);
        const u64 Wi = f2add(Si, DDi);
        const u64 Xr = f2fma(nOneP, DDr, Sr);
        const u64 Xi = f2fma(nOneP, DDi, Si);

        // P = A (.) W = E2 e^{-i d} Fp_rf ;  Q = conj(A) (.) X = E2 e^{+i d} Fm_rf
        const u64 Pr = f2fma(sA,  Wi, f2mul(cA, Wr)) & mFp;
        const u64 Pi = f2fma(nsA, Wr, f2mul(cA, Wi)) & mFp;
        const u64 Qr = f2fma(nsA, Xi, f2mul(cA, Xr)) & mFm;
        const u64 Qi = f2fma(sA,  Xr, f2mul(cA, Xi)) & mFm;

        // Shift: Fp'[2l]=P[2l-1] (prev hi; lane0 -> spec), Fp'[2l+1]=P[2l] (own lo)
        //        Fm'[2l]=Q[2l+1] (own hi),  Fm'[2l+1]=Q[2l+2] (next lo)
        float Plo_r, Phi_r, Plo_i, Phi_i;
        upk2(Pr, Plo_r, Phi_r); upk2(Pi, Plo_i, Phi_i);
        float Qlo_r, Qhi_r, Qlo_i, Qhi_i;
        upk2(Qr, Qlo_r, Qhi_r); upk2(Qi, Qlo_i, Qhi_i);

        float su_r = __shfl_up_sync(FULLMASK, Phi_r, 1);
        float su_i = __shfl_up_sync(FULLMASK, Phi_i, 1);
        float sd_r = __shfl_down_sync(FULLMASK, Qlo_r, 1);
        float sd_i = __shfl_down_sync(FULLMASK, Qlo_i, 1);

        // lane0 Fp'[0] = Q[1] * e^{-2i phi_{p+1}}  (Q[1] = own hi word)
        const float spec_r = Qhi_r * sp_c + Qhi_i * sp_s;
        const float spec_i = Qhi_i * sp_c - Qhi_r * sp_s;
        if (lane == 0) { su_r = spec_r; su_i = spec_i; }

        const u64 Psh_r = pk2(su_r, Plo_r);
        const u64 Psh_i = pk2(su_i, Plo_i);
        const u64 Qsh_r = pk2(Qhi_r, sd_r);
        const u64 Qsh_i = pk2(Qhi_i, sd_i);

        Sr = f2add(Psh_r, Qsh_r);
        Si = f2add(Psh_i, Qsh_i);
        Dr = f2fma(nOneP, Qsh_r, Psh_r);
        Di = f2fma(nOneP, Qsh_i, Psh_i);
        Zr = nZr; Zi = nZi;
    }

    // Final pulse (p = NP-1): |signal| = |Fp_rf[0]| = |S + D''|[0] / 2
    {
        float Sr0, Si0, Dr0, Di0, Zr0, Zi0, dum;
        upk2(Sr, Sr0, dum); upk2(Si, Si0, dum);
        upk2(Dr, Dr0, dum); upk2(Di, Di0, dum);
        upk2(Zr, Zr0, dum); upk2(Zi, Zi0, dum);
        const float DDr0 = ca * Dr0 + sa2 * Zi0;
        const float DDi0 = ca * Di0 - sa2 * Zr0;
        const float Wr0 = Sr0 + DDr0;
        const float Wi0 = Si0 + DDi0;
        if (lane == 0) out[v] = 0.5f * sqrtf(Wr0 * Wr0 + Wi0 * Wi0);
    }
}

extern "C" void kernel_launch(void* const* d_in, const int* in_sizes, int n_in,
                              void* d_out, int out_size)
{
    const float* T1    = (const float*)d_in[0];
    const float* T2    = (const float*)d_in[1];
    const float* alpha = (const float*)d_in[2];
    const float* TR    = (const float*)d_in[3];
    float* out = (float*)d_out;

    const int n = in_sizes[0];
    trig_init_kernel<<<1, 256>>>();
    const int threads = 256;  // 8 warps/block
    const int wpb = threads / 32;
    const int blocks = (n + wpb - 1) / wpb;
    epg_kernel<<<blocks, threads>>>(T1, T2, alpha, TR, out, n);
}

// round 11
// speedup vs baseline: 1.0938x; 1.0938x over previous
#include <cuda_runtime.h>

// EPG / RF-spoiled SPGR, round 11: fixes R10's broken symbol copy.
// (R10 passed the host-side shadow of a __device__ symbol as the memcpy
// SOURCE; constants stayed zero -> rel_err 7.6e-2. Now both symbol
// addresses are resolved via cudaGetSymbolAddress.)
//
// R7 math (best passing, 1823us) + trig tables in __constant__ memory
// (uniform LDC port instead of MIO/LDS).
// Rotating-frame formulation: state (S, D, Z), S = F̂p+F̂m, D = F̂p−F̂m with
// F̂p = e^{-i phi}Fp, F̂m = e^{+i phi}Fm. RF pulse = real 2x2 (D,Z) mix; S is
// invariant. Phase enters only as e^{±i delta_p} unit factors at the shift
// (delta exact fp32 subtraction) and e^{-2i phi_{p+1}} on the Fm[1]->Fp[0]
// element (lane-0 local). One warp per voxel; lane l holds packed state pair
// {k=2l, k=2l+1} (f32x2). Truncation (pre-shift: Fp kill k>=49, Fm kill
// k>=50) via 64-bit ANDs.

#define FULLMASK 0xffffffffu
typedef unsigned long long u64;
#define NP 200

// Staging (written by init kernel), then copied D2D into __constant__.
__device__    float4 g_tab4[NP];   // {cos d, cos d, sin d, sin d}
__device__    float2 g_spec2[NP];  // {cos 2phi_{p+1}, sin 2phi_{p+1}}
__constant__  float4 c_tab4[NP];
__constant__  float2 c_spec2[NP];

__global__ void trig_init_kernel() {
    int p = threadIdx.x + blockIdx.x * blockDim.x;
    if (p >= NP) return;
    const float SPOIL = 2.0420352248333655f;  // float32(deg2rad(117))
    float phi = 0.f, inc = 0.f;
    for (int j = 0; j < p; ++j) { inc += SPOIL; phi += inc; }   // phi_p, exact ref order
    float phin = phi + (inc + SPOIL);                            // phi_{p+1}
    float d = phin - phi;                                        // exact subtraction
    float sd, cd;  sincosf(d, &sd, &cd);
    float s2p, c2p; sincosf(2.0f * phin, &s2p, &c2p);
    g_tab4[p]  = make_float4(cd, cd, sd, sd);
    g_spec2[p] = make_float2(c2p, s2p);
}

static __device__ __forceinline__ u64 pk2(float lo, float hi) {
    u64 r; asm("mov.b64 %0, {%1, %2};" : "=l"(r) : "f"(lo), "f"(hi)); return r;
}
static __device__ __forceinline__ void upk2(u64 v, float& lo, float& hi) {
    asm("mov.b64 {%0, %1}, %2;" : "=f"(lo), "=f"(hi) : "l"(v));
}
static __device__ __forceinline__ u64 f2fma(u64 a, u64 b, u64 c) {
    u64 d; asm("fma.rn.f32x2 %0, %1, %2, %3;" : "=l"(d) : "l"(a), "l"(b), "l"(c)); return d;
}
static __device__ __forceinline__ u64 f2mul(u64 a, u64 b) {
    u64 d; asm("mul.rn.f32x2 %0, %1, %2;" : "=l"(d) : "l"(a), "l"(b)); return d;
}
static __device__ __forceinline__ u64 f2add(u64 a, u64 b) {
    u64 d; asm("add.rn.f32x2 %0, %1, %2;" : "=l"(d) : "l"(a), "l"(b)); return d;
}

__global__ void __launch_bounds__(256)
epg_kernel(const float* __restrict__ T1, const float* __restrict__ T2,
           const float* __restrict__ alpha, const float* __restrict__ TR,
           float* __restrict__ out, int n)
{
    const int v    = (blockIdx.x * blockDim.x + threadIdx.x) >> 5;
    const int lane = threadIdx.x & 31;
    if (v >= n) return;

    const float TRv = TR[0];
    const float E1  = expf(-TRv / T1[v]);
    const float E2  = expf(-TRv / T2[v]);
    const float a   = alpha[v];
    float sa, ca; sincosf(a, &sa, &ca);

    const float E2h   = 0.5f * E2;
    const float sa2   = 2.0f * sa;
    const float saE1h = 0.5f * sa * E1;
    const float caE1  = ca * E1;

    const u64 caP     = pk2(ca, ca);
    const u64 sa2P    = pk2(sa2, sa2);
    const u64 nsa2P   = pk2(-sa2, -sa2);
    const u64 caE1P   = pk2(caE1, caE1);
    const u64 saE1hP  = pk2(saE1h, saE1h);
    const u64 nsaE1hP = pk2(-saE1h, -saE1h);
    const u64 E2hP    = pk2(E2h, E2h);
    const u64 nE2hP   = pk2(-E2h, -E2h);
    const u64 nOneP   = pk2(-1.f, -1.f);
    const u64 boostP  = pk2(lane == 0 ? 1.f - E1 : 0.f, 0.f);
    const u64 zeroP   = 0;

    // Truncation masks (pre-shift): Fp-path kill k>=49, Fm-path kill k>=50.
    const int kLo = 2 * lane, kHi = 2 * lane + 1;
    const u64 mFp = (kLo <= 48 ? 0xffffffffull : 0ull) | (kHi <= 48 ? 0xffffffff00000000ull : 0ull);
    const u64 mFm = (kLo <= 49 ? 0xffffffffull : 0ull) | (kHi <= 49 ? 0xffffffff00000000ull : 0ull);

    // Rotating-frame state {k=2l, k=2l+1}: S = F̂p+F̂m, D = F̂p-F̂m, Z.
    u64 Sr = 0, Si = 0, Dr = 0, Di = 0;
    u64 Zr = pk2(lane == 0 ? 1.f : 0.f, 0.f), Zi = 0;

    #pragma unroll 4
    for (int p = 0; p < NP - 1; ++p) {
        const float4 t = c_tab4[p];                 // {cd,cd,sd,sd} (uniform LDC)
        const u64 cdP = pk2(t.x, t.y);
        const u64 sdP = pk2(t.z, t.w);
        const float2 sp = c_spec2[p];               // {cos 2phi', sin 2phi'}

        // Per-pulse coefficients: A = E2h * e^{-i d}  (Ar=cA, Ai=-sA)
        const u64 cA  = f2mul(E2hP, cdP);
        const u64 sA  = f2mul(E2hP, sdP);
        const u64 nsA = f2mul(nE2hP, sdP);

        // RF rotation (frame): D'' = ca*D - 2i*sa*Z
        //   D''r = ca*Dr + sa2*Zi ; D''i = ca*Di - sa2*Zr
        const u64 DDr = f2fma(caP, Dr, f2mul(sa2P,  Zi));
        const u64 DDi = f2fma(caP, Di, f2mul(nsa2P, Zr));
        // Z_next = E1*(ca*Z - 0.5i*sa*D) + boost
        const u64 nZr = f2fma(caE1P, Zr, f2fma(saE1hP,  Di, boostP));
        const u64 nZi = f2fma(caE1P, Zi, f2fma(nsaE1hP, Dr, zeroP));

        // W = S + D'' (= 2*Fp_rf),  X = S - D'' (= 2*Fm_rf)
        const u64 Wr = f2add(Sr, DDr);
        const u64 Wi = f2add(Si, DDi);
        const u64 Xr = f2fma(nOneP, DDr, Sr);
        const u64 Xi = f2fma(nOneP, DDi, Si);

        // P = A (.) W = E2 e^{-i d} Fp_rf ;  Q = conj(A) (.) X = E2 e^{+i d} Fm_rf
        const u64 Pr = f2fma(sA,  Wi, f2mul(cA, Wr)) & mFp;
        const u64 Pi = f2fma(nsA, Wr, f2mul(cA, Wi)) & mFp;
        const u64 Qr = f2fma(nsA, Xi, f2mul(cA, Xr)) & mFm;
        const u64 Qi = f2fma(sA,  Xr, f2mul(cA, Xi)) & mFm;

        // Shift: Fp'[2l]=P[2l-1] (prev hi; lane0 -> spec), Fp'[2l+1]=P[2l] (own lo)
        //        Fm'[2l]=Q[2l+1] (own hi),  Fm'[2l+1]=Q[2l+2] (next lo)
        float Plo_r, Phi_r, Plo_i, Phi_i;
        upk2(Pr, Plo_r, Phi_r); upk2(Pi, Plo_i, Phi_i);
        float Qlo_r, Qhi_r, Qlo_i, Qhi_i;
        upk2(Qr, Qlo_r, Qhi_r); upk2(Qi, Qlo_i, Qhi_i);

        float su_r = __shfl_up_sync(FULLMASK, Phi_r, 1);
        float su_i = __shfl_up_sync(FULLMASK, Phi_i, 1);
        float sd_r = __shfl_down_sync(FULLMASK, Qlo_r, 1);
        float sd_i = __shfl_down_sync(FULLMASK, Qlo_i, 1);

        // lane0 Fp'[0] = Q[1] * e^{-2i phi_{p+1}}  (Q[1] = own hi word)
        const float spec_r = Qhi_r * sp.x + Qhi_i * sp.y;
        const float spec_i = Qhi_i * sp.x - Qhi_r * sp.y;
        if (lane == 0) { su_r = spec_r; su_i = spec_i; }

        const u64 Psh_r = pk2(su_r, Plo_r);
        const u64 Psh_i = pk2(su_i, Plo_i);
        const u64 Qsh_r = pk2(Qhi_r, sd_r);
        const u64 Qsh_i = pk2(Qhi_i, sd_i);

        Sr = f2add(Psh_r, Qsh_r);
        Si = f2add(Psh_i, Qsh_i);
        Dr = f2fma(nOneP, Qsh_r, Psh_r);
        Di = f2fma(nOneP, Qsh_i, Psh_i);
        Zr = nZr; Zi = nZi;
    }

    // Final pulse (p = NP-1): |signal| = |Fp_rf[0]| = |S + D''|[0] / 2
    {
        float Sr0, Si0, Dr0, Di0, Zr0, Zi0, dum;
        upk2(Sr, Sr0, dum); upk2(Si, Si0, dum);
        upk2(Dr, Dr0, dum); upk2(Di, Di0, dum);
        upk2(Zr, Zr0, dum); upk2(Zi, Zi0, dum);
        const float DDr0 = ca * Dr0 + sa2 * Zi0;
        const float DDi0 = ca * Di0 - sa2 * Zr0;
        const float Wr0 = Sr0 + DDr0;
        const float Wi0 = Si0 + DDi0;
        if (lane == 0) out[v] = 0.5f * sqrtf(Wr0 * Wr0 + Wi0 * Wi0);
    }
}

extern "C" void kernel_launch(void* const* d_in, const int* in_sizes, int n_in,
                              void* d_out, int out_size)
{
    const float* T1    = (const float*)d_in[0];
    const float* T2    = (const float*)d_in[1];
    const float* alpha = (const float*)d_in[2];
    const float* TR    = (const float*)d_in[3];
    float* out = (float*)d_out;

    const int n = in_sizes[0];
    trig_init_kernel<<<1, 256>>>();

    // Resolve REAL device addresses of the symbols (address query only; no
    // allocation, no sync — legal during graph capture), then async D2D copy
    // staging -> constant bank.
    void *p_ctab = 0, *p_gtab = 0, *p_cspec = 0, *p_gspec = 0;
    cudaGetSymbolAddress(&p_ctab,  c_tab4);
    cudaGetSymbolAddress(&p_gtab,  g_tab4);
    cudaGetSymbolAddress(&p_cspec, c_spec2);
    cudaGetSymbolAddress(&p_gspec, g_spec2);
    cudaMemcpyAsync(p_ctab,  p_gtab,  sizeof(float4) * NP, cudaMemcpyDeviceToDevice);
    cudaMemcpyAsync(p_cspec, p_gspec, sizeof(float2) * NP, cudaMemcpyDeviceToDevice);

    const int threads = 256;  // 8 warps/block
    const int wpb = threads / 32;
    const int blocks = (n + wpb - 1) / wpb;
    epg_kernel<<<blocks, threads>>>(T1, T2, alpha, TR, out, n);
}

// round 12
// speedup vs baseline: 1.1739x; 1.0732x over previous
#include <cuda_runtime.h>

// EPG / RF-spoiled SPGR, round 12.
// vs R11 (1732us): (a) state kept directly as (P,Q,Z)=(F̂p,F̂m,Z) using
// G = c2*(P-Q) - i*sa*Z, Fp'' = Q+G, Fm'' = P-G (c2+s2=1 identity) — removes
// the S/D recombination (27 -> 25 packed fma ops/pulse); (b) lazy truncation:
// only Fp[49] needs active killing pre-shift (all k>=50 states stay zero by
// induction), so 4 u64 masks -> 1 single-lane mask on P (8 -> 4 LOP3/pulse).
// Trig tables in __constant__ (uniform LDC). One warp per voxel; lane l holds
// packed state pair {k=2l, k=2l+1} (f32x2). Rotating frame: phase enters only
// as e^{±i delta_p} at the shift + e^{-2i phi_{p+1}} on Fm[1]->Fp[0].

#define FULLMASK 0xffffffffu
typedef unsigned long long u64;
#define NP 200

// Staging (written by init kernel), then copied D2D into __constant__.
__device__    float4 g_tab4[NP];   // {cos d, cos d, sin d, sin d}
__device__    float2 g_spec2[NP];  // {cos 2phi_{p+1}, sin 2phi_{p+1}}
__constant__  float4 c_tab4[NP];
__constant__  float2 c_spec2[NP];

__global__ void trig_init_kernel() {
    int p = threadIdx.x + blockIdx.x * blockDim.x;
    if (p >= NP) return;
    const float SPOIL = 2.0420352248333655f;  // float32(deg2rad(117))
    float phi = 0.f, inc = 0.f;
    for (int j = 0; j < p; ++j) { inc += SPOIL; phi += inc; }   // phi_p, exact ref order
    float phin = phi + (inc + SPOIL);                            // phi_{p+1}
    float d = phin - phi;                                        // exact subtraction
    float sd, cd;  sincosf(d, &sd, &cd);
    float s2p, c2p; sincosf(2.0f * phin, &s2p, &c2p);
    g_tab4[p]  = make_float4(cd, cd, sd, sd);
    g_spec2[p] = make_float2(c2p, s2p);
}

static __device__ __forceinline__ u64 pk2(float lo, float hi) {
    u64 r; asm("mov.b64 %0, {%1, %2};" : "=l"(r) : "f"(lo), "f"(hi)); return r;
}
static __device__ __forceinline__ void upk2(u64 v, float& lo, float& hi) {
    asm("mov.b64 {%0, %1}, %2;" : "=f"(lo), "=f"(hi) : "l"(v));
}
static __device__ __forceinline__ u64 f2fma(u64 a, u64 b, u64 c) {
    u64 d; asm("fma.rn.f32x2 %0, %1, %2, %3;" : "=l"(d) : "l"(a), "l"(b), "l"(c)); return d;
}
static __device__ __forceinline__ u64 f2mul(u64 a, u64 b) {
    u64 d; asm("mul.rn.f32x2 %0, %1, %2;" : "=l"(d) : "l"(a), "l"(b)); return d;
}
static __device__ __forceinline__ u64 f2add(u64 a, u64 b) {
    u64 d; asm("add.rn.f32x2 %0, %1, %2;" : "=l"(d) : "l"(a), "l"(b)); return d;
}

__global__ void __launch_bounds__(256)
epg_kernel(const float* __restrict__ T1, const float* __restrict__ T2,
           const float* __restrict__ alpha, const float* __restrict__ TR,
           float* __restrict__ out, int n)
{
    const int v    = (blockIdx.x * blockDim.x + threadIdx.x) >> 5;
    const int lane = threadIdx.x & 31;
    if (v >= n) return;

    const float TRv = TR[0];
    const float E1  = expf(-TRv / T1[v]);
    const float E2  = expf(-TRv / T2[v]);
    const float a   = alpha[v];
    float sa, ca; sincosf(a, &sa, &ca);
    const float c2    = 0.5f * (1.0f + ca);   // cos^2(a/2)
    const float saE1h = 0.5f * sa * E1;
    const float caE1  = ca * E1;

    const u64 c2P     = pk2(c2, c2);
    const u64 saP     = pk2(sa, sa);
    const u64 nsaP    = pk2(-sa, -sa);
    const u64 caE1P   = pk2(caE1, caE1);
    const u64 saE1hP  = pk2(saE1h, saE1h);
    const u64 nsaE1hP = pk2(-saE1h, -saE1h);
    const u64 E2P     = pk2(E2, E2);
    const u64 nE2P    = pk2(-E2, -E2);
    const u64 nOneP   = pk2(-1.f, -1.f);
    const u64 boostP  = pk2(lane == 0 ? 1.f - E1 : 0.f, 0.f);

    // Lazy truncation: only Fp[49] (lane 24, hi word) must be killed
    // pre-shift; all k>=50 states remain identically zero by induction.
    const u64 mK = (lane == 24) ? 0x00000000ffffffffull : ~0ull;

    // State {k=2l, k=2l+1}: P = F̂p, Q = F̂m, Z (rotating frame phi_p).
    u64 Pr = 0, Pi = 0, Qr = 0, Qi = 0;
    u64 Zr = pk2(lane == 0 ? 1.f : 0.f, 0.f), Zi = 0;

    #pragma unroll 4
    for (int p = 0; p < NP - 1; ++p) {
        const float4 t = c_tab4[p];                 // {cd,cd,sd,sd} (uniform LDC)
        const u64 cdP = pk2(t.x, t.y);
        const u64 sdP = pk2(t.z, t.w);
        const float2 sp = c_spec2[p];               // {cos 2phi', sin 2phi'}

        // Coefficients: A = E2 * e^{-i d}  (Ar = cA, Ai = -sA)
        const u64 cA  = f2mul(E2P, cdP);
        const u64 sA  = f2mul(E2P, sdP);
        const u64 nsA = f2mul(nE2P, sdP);

        // D = P - Q
        const u64 Dr = f2fma(nOneP, Qr, Pr);
        const u64 Di = f2fma(nOneP, Qi, Pi);

        // G = c2*D - i*sa*Z :  Gr = c2*Dr + sa*Zi ; Gi = c2*Di - sa*Zr
        const u64 Gr = f2fma(c2P, Dr, f2mul(saP,  Zi));
        const u64 Gi = f2fma(c2P, Di, f2mul(nsaP, Zr));

        // Z_next = E1*(ca*Z - 0.5i*sa*D) + boost
        const u64 nZr = f2fma(caE1P, Zr, f2fma(saE1hP, Di, boostP));
        const u64 nZi = f2fma(caE1P, Zi, f2mul(nsaE1hP, Dr));

        // Fp'' = Q + G = c2*P + s2*Q - i*sa*Z ;  Fm'' = P - G = s2*P + c2*Q + i*sa*Z
        const u64 Fpr = f2add(Qr, Gr);
        const u64 Fpi = f2add(Qi, Gi);
        const u64 Fmr = f2fma(nOneP, Gr, Pr);
        const u64 Fmi = f2fma(nOneP, Gi, Pi);

        // Pre-shift: nP = A (.) Fp'' (kill Fp[49]) ;  nQ = conj(A) (.) Fm''
        const u64 nPr = f2fma(sA,  Fpi, f2mul(cA, Fpr)) & mK;
        const u64 nPi = f2fma(nsA, Fpr, f2mul(cA, Fpi)) & mK;
        const u64 nQr = f2fma(nsA, Fmi, f2mul(cA, Fmr));
        const u64 nQi = f2fma(sA,  Fmr, f2mul(cA, Fmi));

        // Shift: Fp'[2l]=nP[2l-1] (prev hi; lane0 -> spec), Fp'[2l+1]=nP[2l]
        //        Fm'[2l]=nQ[2l+1] (own hi),  Fm'[2l+1]=nQ[2l+2] (next lo)
        float Plo_r, Phi_r, Plo_i, Phi_i;
        upk2(nPr, Plo_r, Phi_r); upk2(nPi, Plo_i, Phi_i);
        float Qlo_r, Qhi_r, Qlo_i, Qhi_i;
        upk2(nQr, Qlo_r, Qhi_r); upk2(nQi, Qlo_i, Qhi_i);

        float su_r = __shfl_up_sync(FULLMASK, Phi_r, 1);
        float su_i = __shfl_up_sync(FULLMASK, Phi_i, 1);
        float sd_r = __shfl_down_sync(FULLMASK, Qlo_r, 1);
        float sd_i = __shfl_down_sync(FULLMASK, Qlo_i, 1);

        // lane0 Fp'[0] = nQ[1] * e^{-2i phi_{p+1}}  (nQ[1] = own hi word)
        const float spec_r = Qhi_r * sp.x + Qhi_i * sp.y;
        const float spec_i = Qhi_i * sp.x - Qhi_r * sp.y;
        if (lane == 0) { su_r = spec_r; su_i = spec_i; }

        Pr = pk2(su_r, Plo_r);
        Pi = pk2(su_i, Plo_i);
        Qr = pk2(Qhi_r, sd_r);
        Qi = pk2(Qhi_i, sd_i);
        Zr = nZr; Zi = nZi;
    }

    // Final pulse (p = NP-1): signal = |Fp''[0]| = |(Q + G)[0]| (lane 0, lo).
    {
        float P0r, P0i, Q0r, Q0i, Z0r, Z0i, dum;
        upk2(Pr, P0r, dum); upk2(Pi, P0i, dum);
        upk2(Qr, Q0r, dum); upk2(Qi, Q0i, dum);
        upk2(Zr, Z0r, dum); upk2(Zi, Z0i, dum);
        const float D0r = P0r - Q0r;
        const float D0i = P0i - Q0i;
        const float G0r = c2 * D0r + sa * Z0i;
        const float G0i = c2 * D0i - sa * Z0r;
        const float Fp0r = Q0r + G0r;
        const float Fp0i = Q0i + G0i;
        if (lane == 0) out[v] = sqrtf(Fp0r * Fp0r + Fp0i * Fp0i);
    }
}

extern "C" void kernel_launch(void* const* d_in, const int* in_sizes, int n_in,
                              void* d_out, int out_size)
{
    const float* T1    = (const float*)d_in[0];
    const float* T2    = (const float*)d_in[1];
    const float* alpha = (const float*)d_in[2];
    const float* TR    = (const float*)d_in[3];
    float* out = (float*)d_out;

    const int n = in_sizes[0];
    trig_init_kernel<<<1, 256>>>();

    // Resolve REAL device addresses of the symbols (address query only), then
    // async D2D copy staging -> constant bank (capturable memcpy nodes).
    void *p_ctab = 0, *p_gtab = 0, *p_cspec = 0, *p_gspec = 0;
    cudaGetSymbolAddress(&p_ctab,  c_tab4);
    cudaGetSymbolAddress(&p_gtab,  g_tab4);
    cudaGetSymbolAddress(&p_cspec, c_spec2);
    cudaGetSymbolAddress(&p_gspec, g_spec2);
    cudaMemcpyAsync(p_ctab,  p_gtab,  sizeof(float4) * NP, cudaMemcpyDeviceToDevice);
    cudaMemcpyAsync(p_cspec, p_gspec, sizeof(float2) * NP, cudaMemcpyDeviceToDevice);

    const int threads = 256;  // 8 warps/block
    const int wpb = threads / 32;
    const int blocks = (n + wpb - 1) / wpb;
    epg_kernel<<<blocks, threads>>>(T1, T2, alpha, TR, out, n);
}